// round 14
// baseline (speedup 1.0000x reference)
#include <cuda_runtime.h>
#include <cuda_fp16.h>
#include <cstdint>

#define N_   16
#define C_   256
#define CM_  64
#define H_   96
#define W_   96
#define HW_  9216   // 96*96
#define NBLK_ 72    // conv1 blocks per image (HW/128)

// ---------------- scratch (device globals; no allocations) ----------------
__device__ float g_psum[N_ * NBLK_ * C_];
__device__ int   g_wcnt[N_];                // per-image conv1 block counters (self-resetting)
__device__ float g_wdyn[N_ * CM_ * 25];
__device__ float g_watr[N_ * CM_ * 9];
__device__ __half g_fh [N_ * CM_ * HW_];    // f = relu(1x1 conv) in fp16
__device__ __half g_dwh0[N_ * CM_ * HW_];   // depthwise 5x5 out (fp16)
__device__ __half g_dwh1[N_ * CM_ * HW_];   // depthwise atrous out (fp16)
__device__ __half g_cwh[CM_ * C_];          // conv_w in fp16, [o][k]
__device__ __half g_fwh[128 * CM_];         // fuse_w in fp16, [o][k]

// ---------------- helpers ----------------
__device__ __forceinline__ void mma16(float* d, const uint32_t* a, uint32_t b0, uint32_t b1) {
    asm volatile(
        "mma.sync.aligned.m16n8k16.row.col.f32.f16.f16.f32 "
        "{%0,%1,%2,%3},{%4,%5,%6,%7},{%8,%9},{%0,%1,%2,%3};\n"
        : "+f"(d[0]), "+f"(d[1]), "+f"(d[2]), "+f"(d[3])
        : "r"(a[0]), "r"(a[1]), "r"(a[2]), "r"(a[3]), "r"(b0), "r"(b1));
}

__device__ __forceinline__ uint32_t smem_u32(const void* p) {
    return (uint32_t)__cvta_generic_to_shared(p);
}
__device__ __forceinline__ void cp16(uint32_t dst, const void* src) {
    asm volatile("cp.async.cg.shared.global [%0], [%1], 16;" :: "r"(dst), "l"(src));
}
#define CP_COMMIT() asm volatile("cp.async.commit_group;")
#define CP_WAIT(n)  asm volatile("cp.async.wait_group %0;" :: "n"(n))

// ---------------- kernel 0: weight pre-conversion ----------------
__global__ __launch_bounds__(256) void prep_kernel(
    const float* __restrict__ conv_w, const float* __restrict__ fuse_w)
{
    int t = blockIdx.x * 256 + threadIdx.x;
    if (t < CM_ * C_) g_cwh[t] = __float2half_rn(conv_w[t]);
    if (t < 128 * CM_) g_fwh[t] = __float2half_rn(fuse_w[t]);
}

// ---------------- kernel 1: 1x1 conv via fp16 mma + ldmatrix, fused weights tail ----------------
// Block tile: 128 px (M) x 64 outs (N), K=256 in 8 slabs of 32.
// The 72nd block of each image (atomic counter) computes the dynamic dw weights.
__global__ __launch_bounds__(256, 3) void conv1_mma(
    const float* __restrict__ x,
    const float* __restrict__ conv_b,
    const float* __restrict__ conv_w,
    const float* __restrict__ ckw,  const float* __restrict__ ckb,
    const float* __restrict__ ck2w, const float* __restrict__ ck2b,
    const float* __restrict__ kw,   const float* __restrict__ kb,
    const float* __restrict__ k2w,  const float* __restrict__ k2b)
{
    extern __shared__ __align__(16) char smraw[];
    __half* Bs  = (__half*)smraw;              // [64][256] halves, 32 KB
    __half* As0 = (__half*)(smraw + 32768);    // [32][128] halves, 8 KB
    __half* As1 = (__half*)(smraw + 40960);    // 8 KB
    float* smf  = (float*)smraw;               // staging overlay (after final sync)
    __shared__ int   s_flag;
    __shared__ float s_mean[C_];

    int t = threadIdx.x, lane = t & 31, warp = t >> 5;
    int gq = lane >> 2, gr = lane & 3;
    int l8 = lane & 7, grp = lane >> 3;
    int n = blockIdx.y, blk = blockIdx.x;
    int base = blk * 128;
    int wm = warp & 3, wn = warp >> 2;
    const float* xp = x + (size_t)n * C_ * HW_ + base;
    float* psp = g_psum + ((size_t)n * NBLK_ + blk) * C_;

    #pragma unroll
    for (int i = 0; i < 8; ++i) {
        int idx = t + i * 256;
        int o = idx >> 5, ch = idx & 31;
        cp16(smem_u32(Bs + o * 256 + ((ch ^ (o & 7)) << 3)),
             g_cwh + o * 256 + ch * 8);
    }
    CP_COMMIT();

    int krow = t >> 3;
    int px0  = (t & 7) * 16;
    int ch0  = (t & 7) * 2;

    float4 v[4];
    #define LOAD_SLAB(s) do {                                            \
        const float* p_ = xp + (size_t)((s) * 32 + krow) * HW_ + px0;    \
        v[0] = *(const float4*)(p_);                                     \
        v[1] = *(const float4*)(p_ + 4);                                 \
        v[2] = *(const float4*)(p_ + 8);                                 \
        v[3] = *(const float4*)(p_ + 12);                                \
    } while (0)
    #define PSUM_WRITE(s) do {                                           \
        float s_ = v[0].x + v[0].y + v[0].z + v[0].w                     \
                 + v[1].x + v[1].y + v[1].z + v[1].w                     \
                 + v[2].x + v[2].y + v[2].z + v[2].w                     \
                 + v[3].x + v[3].y + v[3].z + v[3].w;                    \
        s_ += __shfl_down_sync(0xffffffffu, s_, 4, 8);                   \
        s_ += __shfl_down_sync(0xffffffffu, s_, 2, 8);                   \
        s_ += __shfl_down_sync(0xffffffffu, s_, 1, 8);                   \
        if ((t & 7) == 0) psp[(s) * 32 + krow] = s_;                     \
    } while (0)
    #define STORE_A2(As) do {                                            \
        __half2 h0 = __floats2half2_rn(v[0].x, v[0].y);                  \
        __half2 h1 = __floats2half2_rn(v[0].z, v[0].w);                  \
        __half2 h2 = __floats2half2_rn(v[1].x, v[1].y);                  \
        __half2 h3 = __floats2half2_rn(v[1].z, v[1].w);                  \
        __half2 h4 = __floats2half2_rn(v[2].x, v[2].y);                  \
        __half2 h5 = __floats2half2_rn(v[2].z, v[2].w);                  \
        __half2 h6 = __floats2half2_rn(v[3].x, v[3].y);                  \
        __half2 h7 = __floats2half2_rn(v[3].z, v[3].w);                  \
        uint4 q0, q1;                                                    \
        q0.x = *(uint32_t*)&h0; q0.y = *(uint32_t*)&h1;                  \
        q0.z = *(uint32_t*)&h2; q0.w = *(uint32_t*)&h3;                  \
        q1.x = *(uint32_t*)&h4; q1.y = *(uint32_t*)&h5;                  \
        q1.z = *(uint32_t*)&h6; q1.w = *(uint32_t*)&h7;                  \
        *(uint4*)((As) + krow * 128 + ((ch0 ^ (krow & 7)) << 3)) = q0;   \
        *(uint4*)((As) + krow * 128 + (((ch0 + 1) ^ (krow & 7)) << 3)) = q1; \
    } while (0)

    float acc[2][4][4];
    #pragma unroll
    for (int a = 0; a < 2; a++)
        #pragma unroll
        for (int b = 0; b < 4; b++)
            #pragma unroll
            for (int c = 0; c < 4; c++) acc[a][b][c] = 0.f;

    LOAD_SLAB(0);
    PSUM_WRITE(0);
    STORE_A2(As0);
    LOAD_SLAB(1);
    CP_WAIT(0);
    __syncthreads();

    for (int slab = 0; slab < 8; ++slab) {
        __half* Ac = (slab & 1) ? As1 : As0;
        #pragma unroll
        for (int g = 0; g < 2; ++g) {
            uint32_t a[2][4];
            #pragma unroll
            for (int mt = 0; mt < 2; ++mt) {
                int k  = g * 16 + ((grp >> 1) << 3) + l8;
                int px = wm * 32 + mt * 16 + ((grp & 1) << 3);
                uint32_t addr = smem_u32(Ac + k * 128 + (((px >> 3) ^ (k & 7)) << 3));
                asm volatile(
                    "ldmatrix.sync.aligned.m8n8.x4.trans.shared.b16 {%0,%1,%2,%3}, [%4];"
                    : "=r"(a[mt][0]), "=r"(a[mt][1]), "=r"(a[mt][2]), "=r"(a[mt][3])
                    : "r"(addr));
            }
            #pragma unroll
            for (int nt = 0; nt < 4; ++nt) {
                int nrow = wn * 32 + nt * 8 + l8;
                int kc = slab * 4 + g * 2 + (grp & 1);
                uint32_t baddr = smem_u32(Bs + nrow * 256 + ((kc ^ (nrow & 7)) << 3));
                uint32_t b0, b1;
                asm volatile(
                    "ldmatrix.sync.aligned.m8n8.x2.shared.b16 {%0,%1}, [%2];"
                    : "=r"(b0), "=r"(b1) : "r"(baddr));
                mma16(acc[0][nt], a[0], b0, b1);
                mma16(acc[1][nt], a[1], b0, b1);
            }
        }
        if (slab < 7) {
            PSUM_WRITE(slab + 1);
            STORE_A2((slab & 1) ? As0 : As1);
            if (slab < 6) LOAD_SLAB(slab + 2);
            __syncthreads();
        }
    }
    __syncthreads();

    // ---- fused weights tail: last block of image n computes dw weights ----
    if (t == 0) {
        __threadfence();   // release this block's psum writes
        int old = atomicAdd(&g_wcnt[n], 1);
        s_flag = (old == NBLK_ - 1) ? 1 : 0;
        if (s_flag) {
            g_wcnt[n] = 0;   // reset for next graph replay
            __threadfence(); // acquire: all 72 blocks' psums now visible
        }
    }
    __syncthreads();
    if (s_flag) {
        const float* pp = g_psum + (size_t)n * NBLK_ * C_ + t;
        float s = 0.f;
        #pragma unroll 8
        for (int b = 0; b < NBLK_; ++b) s += pp[(size_t)b * C_];
        s_mean[t] = s * (1.0f / (float)HW_);
        __syncthreads();
        float a1 = ckw[0],  b1 = ckb[0];
        float a2 = ck2w[0], b2 = ck2b[0];
        for (int c = warp; c < CM_; c += 8) {
            float s2 = 0.f;
            #pragma unroll
            for (int kk = 0; kk < 8; kk++)
                s2 += s_mean[lane + kk * 32] * conv_w[c * C_ + lane + kk * 32];
            #pragma unroll
            for (int o = 16; o > 0; o >>= 1) s2 += __shfl_xor_sync(0xffffffffu, s2, o);
            float g = fmaxf(s2 + conv_b[c], 0.f);
            int idx = n * CM_ + c;
            if (lane < 25) g_wdyn[idx * 25 + lane] = fmaf(a1, fmaf(g, kw[lane],  kb[lane]),  b1);
            if (lane < 9)  g_watr[idx * 9  + lane] = fmaf(a2, fmaf(g, k2w[lane], k2b[lane]), b2);
        }
        __syncthreads();
    }

    // ---- epilogue: stage per-warp 32px x 32out, fp16 coalesced writes ----
    float* st = smf + warp * 1056;
    #pragma unroll
    for (int mt = 0; mt < 2; ++mt)
        #pragma unroll
        for (int nt = 0; nt < 4; ++nt) {
            int pr = mt * 16 + gq, oc = nt * 8 + 2 * gr;
            st[pr * 33 + oc]           = acc[mt][nt][0];
            st[pr * 33 + oc + 1]       = acc[mt][nt][1];
            st[(pr + 8) * 33 + oc]     = acc[mt][nt][2];
            st[(pr + 8) * 33 + oc + 1] = acc[mt][nt][3];
        }
    __syncwarp();
    __half* fp = g_fh + (size_t)n * CM_ * HW_ + base + wm * 32;
    #pragma unroll
    for (int ol = 0; ol < 32; ++ol) {
        int o = wn * 32 + ol;
        float vv = st[lane * 33 + ol] + conv_b[o];
        fp[(size_t)o * HW_ + lane] = __float2half_rn(fmaxf(vv, 0.f));
    }
    #undef LOAD_SLAB
    #undef PSUM_WRITE
    #undef STORE_A2
}

// ---------------- kernel 2: depthwise convs (R12 winner, unchanged) ----------------
__global__ __launch_bounds__(256) void dw_kernel(
    const float* __restrict__ adap_b, const float* __restrict__ atrous_b)
{
    __shared__ float sf[36][100];
    __shared__ float w5[25], w3[9];
    int t  = threadIdx.x;
    int rc = blockIdx.x;   // 0..2 (32-row chunks)
    int c  = blockIdx.y;
    int n  = blockIdx.z;
    int r0 = rc * 32;
    const __half* fp = g_fh + ((size_t)n * CM_ + c) * HW_;

    for (int idx = t; idx < 432; idx += 256) {
        int i = idx / 12, ck = idx - i * 12;
        int grow = r0 - 2 + i;
        float* dst = &sf[i][2 + ck * 8];
        if (grow >= 0 && grow < H_) {
            uint4 q = *(const uint4*)(fp + grow * W_ + ck * 8);
            const __half2* h = (const __half2*)&q;
            *(float2*)(dst + 0) = __half22float2(h[0]);
            *(float2*)(dst + 2) = __half22float2(h[1]);
            *(float2*)(dst + 4) = __half22float2(h[2]);
            *(float2*)(dst + 6) = __half22float2(h[3]);
        } else {
            *(float2*)(dst + 0) = make_float2(0.f, 0.f);
            *(float2*)(dst + 2) = make_float2(0.f, 0.f);
            *(float2*)(dst + 4) = make_float2(0.f, 0.f);
            *(float2*)(dst + 6) = make_float2(0.f, 0.f);
        }
    }
    if (t < 144) {
        int i = t / 4, b = t & 3;
        int j = (b < 2) ? b : 96 + b;   // 0,1,98,99
        sf[i][j] = 0.f;
    }
    if (t < 25) w5[t] = g_wdyn[((size_t)n * CM_ + c) * 25 + t];
    if (t < 9)  w3[t] = g_watr[((size_t)n * CM_ + c) * 9 + t];
    __syncthreads();

    float ab  = adap_b[c];
    float atb = atrous_b[c];
    __half* o0 = g_dwh0 + ((size_t)n * CM_ + c) * HW_;
    __half* o1 = g_dwh1 + ((size_t)n * CM_ + c) * HW_;

    for (int task = t; task < 384; task += 256) {
        int rg = task / 48;
        int c0 = (task - rg * 48) * 2;
        float s[8][6];
        #pragma unroll
        for (int i = 0; i < 8; ++i)
            #pragma unroll
            for (int j = 0; j < 6; ++j)
                s[i][j] = sf[rg * 4 + i][c0 + j];

        float a5[4][2], a3[4][2];
        #pragma unroll
        for (int rr = 0; rr < 4; ++rr) {
            a5[rr][0] = ab;  a5[rr][1] = ab;
            a3[rr][0] = atb; a3[rr][1] = atb;
        }
        #pragma unroll
        for (int i = 0; i < 5; ++i)
            #pragma unroll
            for (int j = 0; j < 5; ++j) {
                float w = w5[i * 5 + j];
                #pragma unroll
                for (int rr = 0; rr < 4; ++rr) {
                    a5[rr][0] = fmaf(w, s[rr + i][j],     a5[rr][0]);
                    a5[rr][1] = fmaf(w, s[rr + i][j + 1], a5[rr][1]);
                }
            }
        #pragma unroll
        for (int i = 0; i < 3; ++i)
            #pragma unroll
            for (int j = 0; j < 3; ++j) {
                float w = w3[i * 3 + j];
                #pragma unroll
                for (int rr = 0; rr < 4; ++rr) {
                    a3[rr][0] = fmaf(w, s[rr + 2 * i][2 * j],     a3[rr][0]);
                    a3[rr][1] = fmaf(w, s[rr + 2 * i][2 * j + 1], a3[rr][1]);
                }
            }

        int rbase = r0 + rg * 4;
        #pragma unroll
        for (int rr = 0; rr < 4; ++rr) {
            *(__half2*)&o0[(rbase + rr) * W_ + c0] =
                __floats2half2_rn(a5[rr][0], a5[rr][1]);
            *(__half2*)&o1[(rbase + rr) * W_ + c0] =
                __floats2half2_rn(a3[rr][0], a3[rr][1]);
        }
    }
}

// ---------------- kernel 3: fuse GEMM, both out-halves per block, split B wait ----------------
// Block tile: 128 px x 128 outs (two 64-out passes), full K=64 resident.
// cp.async group0 = A + B0 (oh=0 needs), group1 = B1 (lands during oh=0 compute).
__global__ __launch_bounds__(256, 3) void fuse_mma(
    float* __restrict__ out,
    const float* __restrict__ fuse_b)
{
    extern __shared__ __align__(16) char smraw[];
    __half* As  = (__half*)smraw;              // [64][128] halves, 16 KB
    __half* Bs0 = (__half*)(smraw + 16384);    // [64][64] halves, 8 KB
    __half* Bs1 = (__half*)(smraw + 24576);    // 8 KB
    float* stg  = (float*)(smraw + 32768);     // staging, 33792 B

    int t = threadIdx.x, lane = t & 31, warp = t >> 5;
    int gq = lane >> 2, gr = lane & 3;
    int l8 = lane & 7, grp = lane >> 3;
    int n = blockIdx.y;
    int br = blockIdx.z;
    int base = blockIdx.x * 128;
    int wm = warp & 3, wn = warp >> 2;
    const __half* dwp = (br ? g_dwh1 : g_dwh0) + (size_t)n * CM_ * HW_ + base;

    // group0: A tile + B half 0
    #pragma unroll
    for (int i = 0; i < 4; ++i) {
        int idx = t + i * 256;
        int c = idx >> 4, ch = idx & 15;
        cp16(smem_u32(As + c * 128 + ((ch ^ (c & 7)) << 3)),
             dwp + (size_t)c * HW_ + ch * 8);
    }
    #pragma unroll
    for (int i = 0; i < 2; ++i) {
        int idx = t + i * 256;
        int o = idx >> 3, ch = idx & 7;
        cp16(smem_u32(Bs0 + o * 64 + ((ch ^ (o & 7)) << 3)),
             g_fwh + (size_t)o * 64 + ch * 8);
    }
    CP_COMMIT();
    // group1: B half 1
    #pragma unroll
    for (int i = 0; i < 2; ++i) {
        int idx = t + i * 256;
        int o = idx >> 3, ch = idx & 7;
        cp16(smem_u32(Bs1 + o * 64 + ((ch ^ (o & 7)) << 3)),
             g_fwh + (size_t)(64 + o) * 64 + ch * 8);
    }
    CP_COMMIT();
    CP_WAIT(1);
    __syncthreads();

    #pragma unroll
    for (int oh = 0; oh < 2; ++oh) {
        __half* Bc = oh ? Bs1 : Bs0;
        if (oh == 1) {
            CP_WAIT(0);
            __syncthreads();
        }
        float acc[2][4][4];
        #pragma unroll
        for (int a = 0; a < 2; a++)
            #pragma unroll
            for (int b = 0; b < 4; b++)
                #pragma unroll
                for (int c = 0; c < 4; c++) acc[a][b][c] = 0.f;

        #pragma unroll
        for (int kk = 0; kk < 4; ++kk) {
            uint32_t a[2][4];
            #pragma unroll
            for (int mt = 0; mt < 2; ++mt) {
                int k  = kk * 16 + ((grp >> 1) << 3) + l8;
                int px = wm * 32 + mt * 16 + ((grp & 1) << 3);
                uint32_t addr = smem_u32(As + k * 128 + (((px >> 3) ^ (k & 7)) << 3));
                asm volatile(
                    "ldmatrix.sync.aligned.m8n8.x4.trans.shared.b16 {%0,%1,%2,%3}, [%4];"
                    : "=r"(a[mt][0]), "=r"(a[mt][1]), "=r"(a[mt][2]), "=r"(a[mt][3])
                    : "r"(addr));
            }
            #pragma unroll
            for (int nt = 0; nt < 4; ++nt) {
                int nrow = wn * 32 + nt * 8 + l8;
                int kc = kk * 2 + (grp & 1);
                uint32_t baddr = smem_u32(Bc + nrow * 64 + ((kc ^ (nrow & 7)) << 3));
                uint32_t b0, b1;
                asm volatile(
                    "ldmatrix.sync.aligned.m8n8.x2.shared.b16 {%0,%1}, [%2];"
                    : "=r"(b0), "=r"(b1) : "r"(baddr));
                mma16(acc[0][nt], a[0], b0, b1);
                mma16(acc[1][nt], a[1], b0, b1);
            }
        }

        // epilogue (per-warp staging; warp-local sync only)
        float* st = stg + warp * 1056;
        __syncwarp();
        #pragma unroll
        for (int mt = 0; mt < 2; ++mt)
            #pragma unroll
            for (int nt = 0; nt < 4; ++nt) {
                int pr = mt * 16 + gq, oc = nt * 8 + 2 * gr;
                st[pr * 33 + oc]           = acc[mt][nt][0];
                st[pr * 33 + oc + 1]       = acc[mt][nt][1];
                st[(pr + 8) * 33 + oc]     = acc[mt][nt][2];
                st[(pr + 8) * 33 + oc + 1] = acc[mt][nt][3];
            }
        __syncwarp();
        float* yp = out + ((size_t)n * 256 + (size_t)br * 128 + (size_t)oh * 64 + (size_t)wn * 32) * HW_
                    + base + wm * 32;
        #pragma unroll
        for (int ol = 0; ol < 32; ++ol) {
            float v = st[lane * 33 + ol] + fuse_b[oh * 64 + wn * 32 + ol];
            yp[(size_t)ol * HW_ + lane] = v;
        }
    }
}

// ---------------- launcher ----------------
#define CONV1_SMEM 49152             // Bs 32K + 2x A 8K; staging (33792) fits
#define FUSE_SMEM  (32768 + 33792)   // tiles 32K + staging 33792

extern "C" void kernel_launch(void* const* d_in, const int* in_sizes, int n_in,
                              void* d_out, int out_size) {
    const float* x        = (const float*)d_in[0];
    const float* conv_w   = (const float*)d_in[1];
    const float* conv_b   = (const float*)d_in[2];
    const float* ckw      = (const float*)d_in[3];
    const float* ckb      = (const float*)d_in[4];
    const float* ck2w     = (const float*)d_in[5];
    const float* ck2b     = (const float*)d_in[6];
    const float* kw       = (const float*)d_in[7];
    const float* kb       = (const float*)d_in[8];
    const float* k2w      = (const float*)d_in[9];
    const float* k2b      = (const float*)d_in[10];
    const float* fuse_w   = (const float*)d_in[11];
    const float* fuse_b   = (const float*)d_in[12];
    const float* adap_b   = (const float*)d_in[13];
    const float* atrous_b = (const float*)d_in[14];
    float* out = (float*)d_out;

    cudaFuncSetAttribute(conv1_mma, cudaFuncAttributeMaxDynamicSharedMemorySize, CONV1_SMEM);
    cudaFuncSetAttribute(fuse_mma,  cudaFuncAttributeMaxDynamicSharedMemorySize, FUSE_SMEM);

    prep_kernel<<<64, 256>>>(conv_w, fuse_w);
    conv1_mma<<<dim3(NBLK_, N_), 256, CONV1_SMEM>>>(
        x, conv_b, conv_w, ckw, ckb, ck2w, ck2b, kw, kb, k2w, k2b);
    dw_kernel<<<dim3(3, CM_, N_), 256>>>(adap_b, atrous_b);
    fuse_mma<<<dim3(HW_ / 128, N_, 2), 256, FUSE_SMEM>>>(out, fuse_b);
}

// round 15
// speedup vs baseline: 1.1334x; 1.1334x over previous
#include <cuda_runtime.h>
#include <cuda_fp16.h>
#include <cstdint>

#define N_   16
#define C_   256
#define CM_  64
#define H_   96
#define W_   96
#define HW_  9216   // 96*96
#define NBLK_ 72    // conv1 blocks per image (HW/128)

// ---------------- scratch (device globals; no allocations) ----------------
__device__ float g_psum[N_ * NBLK_ * C_];
__device__ float g_wdyn[N_ * CM_ * 25];
__device__ float g_watr[N_ * CM_ * 9];
__device__ __half g_fh [N_ * CM_ * HW_];    // f = relu(1x1 conv) in fp16
__device__ __half g_dwh0[N_ * CM_ * HW_];   // depthwise 5x5 out (fp16)
__device__ __half g_dwh1[N_ * CM_ * HW_];   // depthwise atrous out (fp16)
__device__ __half g_cwh[CM_ * C_];          // conv_w in fp16, [o][k]
__device__ __half g_fwh[128 * CM_];         // fuse_w in fp16, [o][k]

// ---------------- helpers ----------------
__device__ __forceinline__ void mma16(float* d, const uint32_t* a, uint32_t b0, uint32_t b1) {
    asm volatile(
        "mma.sync.aligned.m16n8k16.row.col.f32.f16.f16.f32 "
        "{%0,%1,%2,%3},{%4,%5,%6,%7},{%8,%9},{%0,%1,%2,%3};\n"
        : "+f"(d[0]), "+f"(d[1]), "+f"(d[2]), "+f"(d[3])
        : "r"(a[0]), "r"(a[1]), "r"(a[2]), "r"(a[3]), "r"(b0), "r"(b1));
}

__device__ __forceinline__ uint32_t smem_u32(const void* p) {
    return (uint32_t)__cvta_generic_to_shared(p);
}
__device__ __forceinline__ void cp16(uint32_t dst, const void* src) {
    asm volatile("cp.async.cg.shared.global [%0], [%1], 16;" :: "r"(dst), "l"(src));
}
#define CP_COMMIT() asm volatile("cp.async.commit_group;")
#define CP_WAIT(n)  asm volatile("cp.async.wait_group %0;" :: "n"(n))

// ---------------- kernel 0: weight pre-conversion ----------------
__global__ __launch_bounds__(256) void prep_kernel(
    const float* __restrict__ conv_w, const float* __restrict__ fuse_w)
{
    int t = blockIdx.x * 256 + threadIdx.x;
    if (t < CM_ * C_) g_cwh[t] = __float2half_rn(conv_w[t]);
    if (t < 128 * CM_) g_fwh[t] = __float2half_rn(fuse_w[t]);
}

// ---------------- kernel 1: 1x1 conv via fp16 mma + ldmatrix ----------------
// Block tile: 128 px (M) x 64 outs (N), K=256 in 8 slabs of 32.
// B-fragment prefetch per k16 group; vectorized [oc][px] epilogue.
__global__ __launch_bounds__(256) void conv1_mma(
    const float* __restrict__ x,
    const float* __restrict__ conv_b)
{
    extern __shared__ __align__(16) char smraw[];
    __half* Bs  = (__half*)smraw;              // [64][256] halves, 32 KB
    __half* As0 = (__half*)(smraw + 32768);    // [32][128] halves, 8 KB
    __half* As1 = (__half*)(smraw + 40960);    // 8 KB
    float* smf  = (float*)smraw;               // staging overlay (after final sync)

    int t = threadIdx.x, lane = t & 31, warp = t >> 5;
    int gq = lane >> 2, gr = lane & 3;
    int l8 = lane & 7, grp = lane >> 3;
    int n = blockIdx.y, blk = blockIdx.x;
    int base = blk * 128;
    int wm = warp & 3, wn = warp >> 2;
    const float* xp = x + (size_t)n * C_ * HW_ + base;
    float* psp = g_psum + ((size_t)n * NBLK_ + blk) * C_;

    #pragma unroll
    for (int i = 0; i < 8; ++i) {
        int idx = t + i * 256;
        int o = idx >> 5, ch = idx & 31;
        cp16(smem_u32(Bs + o * 256 + ((ch ^ (o & 7)) << 3)),
             g_cwh + o * 256 + ch * 8);
    }
    CP_COMMIT();

    int krow = t >> 3;
    int px0  = (t & 7) * 16;
    int ch0  = (t & 7) * 2;

    float4 v[4];
    #define LOAD_SLAB(s) do {                                            \
        const float* p_ = xp + (size_t)((s) * 32 + krow) * HW_ + px0;    \
        v[0] = *(const float4*)(p_);                                     \
        v[1] = *(const float4*)(p_ + 4);                                 \
        v[2] = *(const float4*)(p_ + 8);                                 \
        v[3] = *(const float4*)(p_ + 12);                                \
    } while (0)
    #define PSUM_WRITE(s) do {                                           \
        float s_ = v[0].x + v[0].y + v[0].z + v[0].w                     \
                 + v[1].x + v[1].y + v[1].z + v[1].w                     \
                 + v[2].x + v[2].y + v[2].z + v[2].w                     \
                 + v[3].x + v[3].y + v[3].z + v[3].w;                    \
        s_ += __shfl_down_sync(0xffffffffu, s_, 4, 8);                   \
        s_ += __shfl_down_sync(0xffffffffu, s_, 2, 8);                   \
        s_ += __shfl_down_sync(0xffffffffu, s_, 1, 8);                   \
        if ((t & 7) == 0) psp[(s) * 32 + krow] = s_;                     \
    } while (0)
    #define STORE_A2(As) do {                                            \
        __half2 h0 = __floats2half2_rn(v[0].x, v[0].y);                  \
        __half2 h1 = __floats2half2_rn(v[0].z, v[0].w);                  \
        __half2 h2 = __floats2half2_rn(v[1].x, v[1].y);                  \
        __half2 h3 = __floats2half2_rn(v[1].z, v[1].w);                  \
        __half2 h4 = __floats2half2_rn(v[2].x, v[2].y);                  \
        __half2 h5 = __floats2half2_rn(v[2].z, v[2].w);                  \
        __half2 h6 = __floats2half2_rn(v[3].x, v[3].y);                  \
        __half2 h7 = __floats2half2_rn(v[3].z, v[3].w);                  \
        uint4 q0, q1;                                                    \
        q0.x = *(uint32_t*)&h0; q0.y = *(uint32_t*)&h1;                  \
        q0.z = *(uint32_t*)&h2; q0.w = *(uint32_t*)&h3;                  \
        q1.x = *(uint32_t*)&h4; q1.y = *(uint32_t*)&h5;                  \
        q1.z = *(uint32_t*)&h6; q1.w = *(uint32_t*)&h7;                  \
        *(uint4*)((As) + krow * 128 + ((ch0 ^ (krow & 7)) << 3)) = q0;   \
        *(uint4*)((As) + krow * 128 + (((ch0 + 1) ^ (krow & 7)) << 3)) = q1; \
    } while (0)

    float acc[2][4][4];
    #pragma unroll
    for (int a = 0; a < 2; a++)
        #pragma unroll
        for (int b = 0; b < 4; b++)
            #pragma unroll
            for (int c = 0; c < 4; c++) acc[a][b][c] = 0.f;

    LOAD_SLAB(0);
    PSUM_WRITE(0);
    STORE_A2(As0);
    LOAD_SLAB(1);
    CP_WAIT(0);
    __syncthreads();

    for (int slab = 0; slab < 8; ++slab) {
        __half* Ac = (slab & 1) ? As1 : As0;
        #pragma unroll
        for (int g = 0; g < 2; ++g) {
            uint32_t a[2][4];
            #pragma unroll
            for (int mt = 0; mt < 2; ++mt) {
                int k  = g * 16 + ((grp >> 1) << 3) + l8;
                int px = wm * 32 + mt * 16 + ((grp & 1) << 3);
                uint32_t addr = smem_u32(Ac + k * 128 + (((px >> 3) ^ (k & 7)) << 3));
                asm volatile(
                    "ldmatrix.sync.aligned.m8n8.x4.trans.shared.b16 {%0,%1,%2,%3}, [%4];"
                    : "=r"(a[mt][0]), "=r"(a[mt][1]), "=r"(a[mt][2]), "=r"(a[mt][3])
                    : "r"(addr));
            }
            // prefetch ALL B fragments for this k16 group, then mma chain
            uint32_t bf[4][2];
            #pragma unroll
            for (int nt = 0; nt < 4; ++nt) {
                int nrow = wn * 32 + nt * 8 + l8;
                int kc = slab * 4 + g * 2 + (grp & 1);
                uint32_t baddr = smem_u32(Bs + nrow * 256 + ((kc ^ (nrow & 7)) << 3));
                asm volatile(
                    "ldmatrix.sync.aligned.m8n8.x2.shared.b16 {%0,%1}, [%2];"
                    : "=r"(bf[nt][0]), "=r"(bf[nt][1]) : "r"(baddr));
            }
            #pragma unroll
            for (int nt = 0; nt < 4; ++nt) {
                mma16(acc[0][nt], a[0], bf[nt][0], bf[nt][1]);
                mma16(acc[1][nt], a[1], bf[nt][0], bf[nt][1]);
            }
        }
        if (slab < 7) {
            PSUM_WRITE(slab + 1);
            STORE_A2((slab & 1) ? As0 : As1);
            if (slab < 6) LOAD_SLAB(slab + 2);
            __syncthreads();
        }
    }
    __syncthreads();

    // ---- epilogue: per-warp [oc][px] stride-36 staging, 8B half4 stores ----
    float* st = smf + warp * 1152;   // 32*36
    #pragma unroll
    for (int mt = 0; mt < 2; ++mt)
        #pragma unroll
        for (int nt = 0; nt < 4; ++nt) {
            int pr = mt * 16 + gq, oc = nt * 8 + 2 * gr;
            st[oc * 36 + pr]           = acc[mt][nt][0];
            st[(oc + 1) * 36 + pr]     = acc[mt][nt][1];
            st[oc * 36 + pr + 8]       = acc[mt][nt][2];
            st[(oc + 1) * 36 + pr + 8] = acc[mt][nt][3];
        }
    __syncwarp();
    __half* fp = g_fh + (size_t)n * CM_ * HW_ + base + wm * 32;
    int c4 = lane & 7, orow = lane >> 3;
    #pragma unroll
    for (int it = 0; it < 8; ++it) {
        int o = it * 4 + orow;
        float4 vv = *(const float4*)&st[o * 36 + c4 * 4];
        float bv = conv_b[wn * 32 + o];
        __half2 h01 = __floats2half2_rn(fmaxf(vv.x + bv, 0.f), fmaxf(vv.y + bv, 0.f));
        __half2 h23 = __floats2half2_rn(fmaxf(vv.z + bv, 0.f), fmaxf(vv.w + bv, 0.f));
        uint2 q;
        q.x = *(uint32_t*)&h01; q.y = *(uint32_t*)&h23;
        *(uint2*)(fp + (size_t)(wn * 32 + o) * HW_ + c4 * 4) = q;
    }
    #undef LOAD_SLAB
    #undef PSUM_WRITE
    #undef STORE_A2
}

// ---------------- kernel 2: finish mean + g + dynamic depthwise weights ----------------
__global__ __launch_bounds__(256) void weights_kernel(
    const float* __restrict__ conv_w, const float* __restrict__ conv_b,
    const float* __restrict__ ckw,  const float* __restrict__ ckb,
    const float* __restrict__ ck2w, const float* __restrict__ ck2b,
    const float* __restrict__ kw,   const float* __restrict__ kb,
    const float* __restrict__ k2w,  const float* __restrict__ k2b)
{
    __shared__ float sm[C_];
    int n = blockIdx.x;
    int t = threadIdx.x;
    {
        const float* pp = g_psum + (size_t)n * NBLK_ * C_ + t;
        float s = 0.f;
        #pragma unroll 8
        for (int b = 0; b < NBLK_; ++b) s += pp[(size_t)b * C_];
        sm[t] = s * (1.0f / (float)HW_);
    }
    __syncthreads();
    int warp = t >> 5, lane = t & 31;
    float a1 = ckw[0],  b1 = ckb[0];
    float a2 = ck2w[0], b2 = ck2b[0];
    for (int c = warp; c < CM_; c += 8) {
        float s = 0.f;
        #pragma unroll
        for (int kk = 0; kk < 8; kk++)
            s += sm[lane + kk * 32] * conv_w[c * C_ + lane + kk * 32];
        #pragma unroll
        for (int o = 16; o > 0; o >>= 1) s += __shfl_xor_sync(0xffffffffu, s, o);
        float g = fmaxf(s + conv_b[c], 0.f);
        int idx = n * CM_ + c;
        if (lane < 25) g_wdyn[idx * 25 + lane] = fmaf(a1, fmaf(g, kw[lane],  kb[lane]),  b1);
        if (lane < 9)  g_watr[idx * 9  + lane] = fmaf(a2, fmaf(g, k2w[lane], k2b[lane]), b2);
    }
}

// ---------------- kernel 3: depthwise convs (R12 winner, unchanged) ----------------
__global__ __launch_bounds__(256) void dw_kernel(
    const float* __restrict__ adap_b, const float* __restrict__ atrous_b)
{
    __shared__ float sf[36][100];
    __shared__ float w5[25], w3[9];
    int t  = threadIdx.x;
    int rc = blockIdx.x;   // 0..2 (32-row chunks)
    int c  = blockIdx.y;
    int n  = blockIdx.z;
    int r0 = rc * 32;
    const __half* fp = g_fh + ((size_t)n * CM_ + c) * HW_;

    for (int idx = t; idx < 432; idx += 256) {
        int i = idx / 12, ck = idx - i * 12;
        int grow = r0 - 2 + i;
        float* dst = &sf[i][2 + ck * 8];
        if (grow >= 0 && grow < H_) {
            uint4 q = *(const uint4*)(fp + grow * W_ + ck * 8);
            const __half2* h = (const __half2*)&q;
            *(float2*)(dst + 0) = __half22float2(h[0]);
            *(float2*)(dst + 2) = __half22float2(h[1]);
            *(float2*)(dst + 4) = __half22float2(h[2]);
            *(float2*)(dst + 6) = __half22float2(h[3]);
        } else {
            *(float2*)(dst + 0) = make_float2(0.f, 0.f);
            *(float2*)(dst + 2) = make_float2(0.f, 0.f);
            *(float2*)(dst + 4) = make_float2(0.f, 0.f);
            *(float2*)(dst + 6) = make_float2(0.f, 0.f);
        }
    }
    if (t < 144) {
        int i = t / 4, b = t & 3;
        int j = (b < 2) ? b : 96 + b;   // 0,1,98,99
        sf[i][j] = 0.f;
    }
    if (t < 25) w5[t] = g_wdyn[((size_t)n * CM_ + c) * 25 + t];
    if (t < 9)  w3[t] = g_watr[((size_t)n * CM_ + c) * 9 + t];
    __syncthreads();

    float ab  = adap_b[c];
    float atb = atrous_b[c];
    __half* o0 = g_dwh0 + ((size_t)n * CM_ + c) * HW_;
    __half* o1 = g_dwh1 + ((size_t)n * CM_ + c) * HW_;

    for (int task = t; task < 384; task += 256) {
        int rg = task / 48;
        int c0 = (task - rg * 48) * 2;
        float s[8][6];
        #pragma unroll
        for (int i = 0; i < 8; ++i)
            #pragma unroll
            for (int j = 0; j < 6; ++j)
                s[i][j] = sf[rg * 4 + i][c0 + j];

        float a5[4][2], a3[4][2];
        #pragma unroll
        for (int rr = 0; rr < 4; ++rr) {
            a5[rr][0] = ab;  a5[rr][1] = ab;
            a3[rr][0] = atb; a3[rr][1] = atb;
        }
        #pragma unroll
        for (int i = 0; i < 5; ++i)
            #pragma unroll
            for (int j = 0; j < 5; ++j) {
                float w = w5[i * 5 + j];
                #pragma unroll
                for (int rr = 0; rr < 4; ++rr) {
                    a5[rr][0] = fmaf(w, s[rr + i][j],     a5[rr][0]);
                    a5[rr][1] = fmaf(w, s[rr + i][j + 1], a5[rr][1]);
                }
            }
        #pragma unroll
        for (int i = 0; i < 3; ++i)
            #pragma unroll
            for (int j = 0; j < 3; ++j) {
                float w = w3[i * 3 + j];
                #pragma unroll
                for (int rr = 0; rr < 4; ++rr) {
                    a3[rr][0] = fmaf(w, s[rr + 2 * i][2 * j],     a3[rr][0]);
                    a3[rr][1] = fmaf(w, s[rr + 2 * i][2 * j + 1], a3[rr][1]);
                }
            }

        int rbase = r0 + rg * 4;
        #pragma unroll
        for (int rr = 0; rr < 4; ++rr) {
            *(__half2*)&o0[(rbase + rr) * W_ + c0] =
                __floats2half2_rn(a5[rr][0], a5[rr][1]);
            *(__half2*)&o1[(rbase + rr) * W_ + c0] =
                __floats2half2_rn(a3[rr][0], a3[rr][1]);
        }
    }
}

// ---------------- kernel 4: fuse GEMM, both out-halves per block ----------------
// Block tile: 128 px x 128 outs (two 64-out passes), full K=64 resident.
// B-fragment prefetch; vectorized [oc][px] stride-36 epilogue with STG.128.
__global__ __launch_bounds__(256) void fuse_mma(
    float* __restrict__ out,
    const float* __restrict__ fuse_b)
{
    extern __shared__ __align__(16) char smraw[];
    __half* As  = (__half*)smraw;              // [64][128] halves, 16 KB
    __half* Bs0 = (__half*)(smraw + 16384);    // [64][64] halves, 8 KB
    __half* Bs1 = (__half*)(smraw + 24576);    // 8 KB
    float* stg  = (float*)(smraw + 32768);     // staging, 8*1152*4 = 36864 B

    int t = threadIdx.x, lane = t & 31, warp = t >> 5;
    int gq = lane >> 2, gr = lane & 3;
    int l8 = lane & 7, grp = lane >> 3;
    int n = blockIdx.y;
    int br = blockIdx.z;
    int base = blockIdx.x * 128;
    int wm = warp & 3, wn = warp >> 2;
    const __half* dwp = (br ? g_dwh1 : g_dwh0) + (size_t)n * CM_ * HW_ + base;

    #pragma unroll
    for (int i = 0; i < 4; ++i) {
        int idx = t + i * 256;
        int c = idx >> 4, ch = idx & 15;
        cp16(smem_u32(As + c * 128 + ((ch ^ (c & 7)) << 3)),
             dwp + (size_t)c * HW_ + ch * 8);
    }
    #pragma unroll
    for (int i = 0; i < 4; ++i) {
        int idx = t + i * 256;
        int oh = idx >> 9;
        int rem = idx & 511;
        int o = rem >> 3, ch = rem & 7;
        __half* Bd = oh ? Bs1 : Bs0;
        cp16(smem_u32(Bd + o * 64 + ((ch ^ (o & 7)) << 3)),
             g_fwh + (size_t)(oh * 64 + o) * 64 + ch * 8);
    }
    CP_COMMIT();
    CP_WAIT(0);
    __syncthreads();

    int c4 = lane & 7, orow = lane >> 3;

    #pragma unroll
    for (int oh = 0; oh < 2; ++oh) {
        __half* Bc = oh ? Bs1 : Bs0;
        float acc[2][4][4];
        #pragma unroll
        for (int a = 0; a < 2; a++)
            #pragma unroll
            for (int b = 0; b < 4; b++)
                #pragma unroll
                for (int c = 0; c < 4; c++) acc[a][b][c] = 0.f;

        #pragma unroll
        for (int kk = 0; kk < 4; ++kk) {
            uint32_t a[2][4];
            #pragma unroll
            for (int mt = 0; mt < 2; ++mt) {
                int k  = kk * 16 + ((grp >> 1) << 3) + l8;
                int px = wm * 32 + mt * 16 + ((grp & 1) << 3);
                uint32_t addr = smem_u32(As + k * 128 + (((px >> 3) ^ (k & 7)) << 3));
                asm volatile(
                    "ldmatrix.sync.aligned.m8n8.x4.trans.shared.b16 {%0,%1,%2,%3}, [%4];"
                    : "=r"(a[mt][0]), "=r"(a[mt][1]), "=r"(a[mt][2]), "=r"(a[mt][3])
                    : "r"(addr));
            }
            // prefetch ALL B fragments, then mma chain
            uint32_t bf[4][2];
            #pragma unroll
            for (int nt = 0; nt < 4; ++nt) {
                int nrow = wn * 32 + nt * 8 + l8;
                int kc = kk * 2 + (grp & 1);
                uint32_t baddr = smem_u32(Bc + nrow * 64 + ((kc ^ (nrow & 7)) << 3));
                asm volatile(
                    "ldmatrix.sync.aligned.m8n8.x2.shared.b16 {%0,%1}, [%2];"
                    : "=r"(bf[nt][0]), "=r"(bf[nt][1]) : "r"(baddr));
            }
            #pragma unroll
            for (int nt = 0; nt < 4; ++nt) {
                mma16(acc[0][nt], a[0], bf[nt][0], bf[nt][1]);
                mma16(acc[1][nt], a[1], bf[nt][0], bf[nt][1]);
            }
        }

        // ---- epilogue: [oc][px] stride-36 staging, float4 loads + STG.128 ----
        float* st = stg + warp * 1152;
        __syncwarp();
        #pragma unroll
        for (int mt = 0; mt < 2; ++mt)
            #pragma unroll
            for (int nt = 0; nt < 4; ++nt) {
                int pr = mt * 16 + gq, oc = nt * 8 + 2 * gr;
                st[oc * 36 + pr]           = acc[mt][nt][0];
                st[(oc + 1) * 36 + pr]     = acc[mt][nt][1];
                st[oc * 36 + pr + 8]       = acc[mt][nt][2];
                st[(oc + 1) * 36 + pr + 8] = acc[mt][nt][3];
            }
        __syncwarp();
        float* yp = out + ((size_t)n * 256 + (size_t)br * 128 + (size_t)oh * 64 + (size_t)wn * 32) * HW_
                    + base + wm * 32;
        #pragma unroll
        for (int it = 0; it < 8; ++it) {
            int o = it * 4 + orow;
            float4 vv = *(const float4*)&st[o * 36 + c4 * 4];
            float bv = fuse_b[oh * 64 + wn * 32 + o];
            vv.x += bv; vv.y += bv; vv.z += bv; vv.w += bv;
            *(float4*)(yp + (size_t)o * HW_ + c4 * 4) = vv;
        }
    }
}

// ---------------- launcher ----------------
#define CONV1_SMEM 49152             // Bs 32K + 2x A 8K; staging (36864) fits
#define FUSE_SMEM  (32768 + 36864)   // tiles 32K + staging 36864

extern "C" void kernel_launch(void* const* d_in, const int* in_sizes, int n_in,
                              void* d_out, int out_size) {
    const float* x        = (const float*)d_in[0];
    const float* conv_w   = (const float*)d_in[1];
    const float* conv_b   = (const float*)d_in[2];
    const float* ckw      = (const float*)d_in[3];
    const float* ckb      = (const float*)d_in[4];
    const float* ck2w     = (const float*)d_in[5];
    const float* ck2b     = (const float*)d_in[6];
    const float* kw       = (const float*)d_in[7];
    const float* kb       = (const float*)d_in[8];
    const float* k2w      = (const float*)d_in[9];
    const float* k2b      = (const float*)d_in[10];
    const float* fuse_w   = (const float*)d_in[11];
    const float* fuse_b   = (const float*)d_in[12];
    const float* adap_b   = (const float*)d_in[13];
    const float* atrous_b = (const float*)d_in[14];
    float* out = (float*)d_out;

    cudaFuncSetAttribute(conv1_mma, cudaFuncAttributeMaxDynamicSharedMemorySize, CONV1_SMEM);
    cudaFuncSetAttribute(fuse_mma,  cudaFuncAttributeMaxDynamicSharedMemorySize, FUSE_SMEM);

    prep_kernel<<<64, 256>>>(conv_w, fuse_w);
    conv1_mma<<<dim3(NBLK_, N_), 256, CONV1_SMEM>>>(x, conv_b);
    weights_kernel<<<N_, 256>>>(conv_w, conv_b, ckw, ckb, ck2w, ck2b, kw, kb, k2w, k2b);
    dw_kernel<<<dim3(3, CM_, N_), 256>>>(adap_b, atrous_b);
    fuse_mma<<<dim3(HW_ / 128, N_, 2), 256, FUSE_SMEM>>>(out, fuse_b);
}

// round 16
// speedup vs baseline: 1.1400x; 1.0058x over previous
#include <cuda_runtime.h>
#include <cuda_fp16.h>
#include <cstdint>

#define N_   16
#define C_   256
#define CM_  64
#define H_   96
#define W_   96
#define HW_  9216   // 96*96
#define NBLK_ 72    // conv1 blocks per image (HW/128)

// ---------------- scratch (device globals; no allocations) ----------------
__device__ float g_psum[N_ * NBLK_ * C_];
__device__ float g_wdyn[N_ * CM_ * 25];
__device__ float g_watr[N_ * CM_ * 9];
__device__ __half g_fh [N_ * CM_ * HW_];    // f = relu(1x1 conv) in fp16
__device__ __half g_dwh0[N_ * CM_ * HW_];   // depthwise 5x5 out (fp16)
__device__ __half g_dwh1[N_ * CM_ * HW_];   // depthwise atrous out (fp16)

// ---------------- helpers ----------------
__device__ __forceinline__ void mma16(float* d, const uint32_t* a, uint32_t b0, uint32_t b1) {
    asm volatile(
        "mma.sync.aligned.m16n8k16.row.col.f32.f16.f16.f32 "
        "{%0,%1,%2,%3},{%4,%5,%6,%7},{%8,%9},{%0,%1,%2,%3};\n"
        : "+f"(d[0]), "+f"(d[1]), "+f"(d[2]), "+f"(d[3])
        : "r"(a[0]), "r"(a[1]), "r"(a[2]), "r"(a[3]), "r"(b0), "r"(b1));
}

__device__ __forceinline__ uint32_t smem_u32(const void* p) {
    return (uint32_t)__cvta_generic_to_shared(p);
}
__device__ __forceinline__ void cp16(uint32_t dst, const void* src) {
    asm volatile("cp.async.cg.shared.global [%0], [%1], 16;" :: "r"(dst), "l"(src));
}
#define CP_COMMIT() asm volatile("cp.async.commit_group;")
#define CP_WAIT(n)  asm volatile("cp.async.wait_group %0;" :: "n"(n))

// convert 8 consecutive fp32 -> 8 halves packed in uint4
__device__ __forceinline__ uint4 cvt8h(float4 f0, float4 f1) {
    __half2 h0 = __floats2half2_rn(f0.x, f0.y);
    __half2 h1 = __floats2half2_rn(f0.z, f0.w);
    __half2 h2 = __floats2half2_rn(f1.x, f1.y);
    __half2 h3 = __floats2half2_rn(f1.z, f1.w);
    uint4 q;
    q.x = *(uint32_t*)&h0; q.y = *(uint32_t*)&h1;
    q.z = *(uint32_t*)&h2; q.w = *(uint32_t*)&h3;
    return q;
}

// ---------------- kernel 1: 1x1 conv via fp16 mma + ldmatrix ----------------
// Block tile: 128 px (M) x 64 outs (N), K=256 in 8 slabs of 32.
// Weights converted fp32->fp16 during smem fill (prep kernel eliminated).
__global__ __launch_bounds__(256) void conv1_mma(
    const float* __restrict__ x,
    const float* __restrict__ conv_b,
    const float* __restrict__ conv_w)
{
    extern __shared__ __align__(16) char smraw[];
    __half* Bs  = (__half*)smraw;              // [64][256] halves, 32 KB
    __half* As0 = (__half*)(smraw + 32768);    // [32][128] halves, 8 KB
    __half* As1 = (__half*)(smraw + 40960);    // 8 KB
    float* smf  = (float*)smraw;               // staging overlay (after final sync)

    int t = threadIdx.x, lane = t & 31, warp = t >> 5;
    int gq = lane >> 2, gr = lane & 3;
    int l8 = lane & 7, grp = lane >> 3;
    int n = blockIdx.y, blk = blockIdx.x;
    int base = blk * 128;
    int wm = warp & 3, wn = warp >> 2;
    const float* xp = x + (size_t)n * C_ * HW_ + base;
    float* psp = g_psum + ((size_t)n * NBLK_ + blk) * C_;

    // ---- B fill: load fp32 conv_w, convert, swizzled STS (one-time) ----
    #pragma unroll
    for (int i = 0; i < 8; ++i) {
        int idx = t + i * 256;
        int o = idx >> 5, ch = idx & 31;
        const float* src = conv_w + o * 256 + ch * 8;
        float4 f0 = *(const float4*)src;
        float4 f1 = *(const float4*)(src + 4);
        *(uint4*)(Bs + o * 256 + ((ch ^ (o & 7)) << 3)) = cvt8h(f0, f1);
    }

    int krow = t >> 3;
    int px0  = (t & 7) * 16;
    int ch0  = (t & 7) * 2;

    float4 v[4];
    #define LOAD_SLAB(s) do {                                            \
        const float* p_ = xp + (size_t)((s) * 32 + krow) * HW_ + px0;    \
        v[0] = *(const float4*)(p_);                                     \
        v[1] = *(const float4*)(p_ + 4);                                 \
        v[2] = *(const float4*)(p_ + 8);                                 \
        v[3] = *(const float4*)(p_ + 12);                                \
    } while (0)
    #define PSUM_WRITE(s) do {                                           \
        float s_ = v[0].x + v[0].y + v[0].z + v[0].w                     \
                 + v[1].x + v[1].y + v[1].z + v[1].w                     \
                 + v[2].x + v[2].y + v[2].z + v[2].w                     \
                 + v[3].x + v[3].y + v[3].z + v[3].w;                    \
        s_ += __shfl_down_sync(0xffffffffu, s_, 4, 8);                   \
        s_ += __shfl_down_sync(0xffffffffu, s_, 2, 8);                   \
        s_ += __shfl_down_sync(0xffffffffu, s_, 1, 8);                   \
        if ((t & 7) == 0) psp[(s) * 32 + krow] = s_;                     \
    } while (0)
    #define STORE_A2(As) do {                                            \
        *(uint4*)((As) + krow * 128 + ((ch0 ^ (krow & 7)) << 3)) = cvt8h(v[0], v[1]); \
        *(uint4*)((As) + krow * 128 + (((ch0 + 1) ^ (krow & 7)) << 3)) = cvt8h(v[2], v[3]); \
    } while (0)

    float acc[2][4][4];
    #pragma unroll
    for (int a = 0; a < 2; a++)
        #pragma unroll
        for (int b = 0; b < 4; b++)
            #pragma unroll
            for (int c = 0; c < 4; c++) acc[a][b][c] = 0.f;

    LOAD_SLAB(0);
    PSUM_WRITE(0);
    STORE_A2(As0);
    LOAD_SLAB(1);
    __syncthreads();

    for (int slab = 0; slab < 8; ++slab) {
        __half* Ac = (slab & 1) ? As1 : As0;
        #pragma unroll
        for (int g = 0; g < 2; ++g) {
            uint32_t a[2][4];
            #pragma unroll
            for (int mt = 0; mt < 2; ++mt) {
                int k  = g * 16 + ((grp >> 1) << 3) + l8;
                int px = wm * 32 + mt * 16 + ((grp & 1) << 3);
                uint32_t addr = smem_u32(Ac + k * 128 + (((px >> 3) ^ (k & 7)) << 3));
                asm volatile(
                    "ldmatrix.sync.aligned.m8n8.x4.trans.shared.b16 {%0,%1,%2,%3}, [%4];"
                    : "=r"(a[mt][0]), "=r"(a[mt][1]), "=r"(a[mt][2]), "=r"(a[mt][3])
                    : "r"(addr));
            }
            uint32_t bf[4][2];
            #pragma unroll
            for (int nt = 0; nt < 4; ++nt) {
                int nrow = wn * 32 + nt * 8 + l8;
                int kc = slab * 4 + g * 2 + (grp & 1);
                uint32_t baddr = smem_u32(Bs + nrow * 256 + ((kc ^ (nrow & 7)) << 3));
                asm volatile(
                    "ldmatrix.sync.aligned.m8n8.x2.shared.b16 {%0,%1}, [%2];"
                    : "=r"(bf[nt][0]), "=r"(bf[nt][1]) : "r"(baddr));
            }
            #pragma unroll
            for (int nt = 0; nt < 4; ++nt) {
                mma16(acc[0][nt], a[0], bf[nt][0], bf[nt][1]);
                mma16(acc[1][nt], a[1], bf[nt][0], bf[nt][1]);
            }
        }
        if (slab < 7) {
            PSUM_WRITE(slab + 1);
            STORE_A2((slab & 1) ? As0 : As1);
            if (slab < 6) LOAD_SLAB(slab + 2);
            __syncthreads();
        }
    }
    __syncthreads();

    // ---- epilogue: per-warp [oc][px] stride-36 staging, 8B half4 stores ----
    float* st = smf + warp * 1152;   // 32*36
    #pragma unroll
    for (int mt = 0; mt < 2; ++mt)
        #pragma unroll
        for (int nt = 0; nt < 4; ++nt) {
            int pr = mt * 16 + gq, oc = nt * 8 + 2 * gr;
            st[oc * 36 + pr]           = acc[mt][nt][0];
            st[(oc + 1) * 36 + pr]     = acc[mt][nt][1];
            st[oc * 36 + pr + 8]       = acc[mt][nt][2];
            st[(oc + 1) * 36 + pr + 8] = acc[mt][nt][3];
        }
    __syncwarp();
    __half* fp = g_fh + (size_t)n * CM_ * HW_ + base + wm * 32;
    int c4 = lane & 7, orow = lane >> 3;
    #pragma unroll
    for (int it = 0; it < 8; ++it) {
        int o = it * 4 + orow;
        float4 vv = *(const float4*)&st[o * 36 + c4 * 4];
        float bv = conv_b[wn * 32 + o];
        __half2 h01 = __floats2half2_rn(fmaxf(vv.x + bv, 0.f), fmaxf(vv.y + bv, 0.f));
        __half2 h23 = __floats2half2_rn(fmaxf(vv.z + bv, 0.f), fmaxf(vv.w + bv, 0.f));
        uint2 q;
        q.x = *(uint32_t*)&h01; q.y = *(uint32_t*)&h23;
        *(uint2*)(fp + (size_t)(wn * 32 + o) * HW_ + c4 * 4) = q;
    }
    #undef LOAD_SLAB
    #undef PSUM_WRITE
    #undef STORE_A2
}

// ---------------- kernel 2: finish mean + g + dynamic depthwise weights ----------------
__global__ __launch_bounds__(256) void weights_kernel(
    const float* __restrict__ conv_w, const float* __restrict__ conv_b,
    const float* __restrict__ ckw,  const float* __restrict__ ckb,
    const float* __restrict__ ck2w, const float* __restrict__ ck2b,
    const float* __restrict__ kw,   const float* __restrict__ kb,
    const float* __restrict__ k2w,  const float* __restrict__ k2b)
{
    __shared__ float sm[C_];
    int n = blockIdx.x;
    int t = threadIdx.x;
    {
        const float* pp = g_psum + (size_t)n * NBLK_ * C_ + t;
        float s = 0.f;
        #pragma unroll 8
        for (int b = 0; b < NBLK_; ++b) s += pp[(size_t)b * C_];
        sm[t] = s * (1.0f / (float)HW_);
    }
    __syncthreads();
    int warp = t >> 5, lane = t & 31;
    float a1 = ckw[0],  b1 = ckb[0];
    float a2 = ck2w[0], b2 = ck2b[0];
    for (int c = warp; c < CM_; c += 8) {
        float s = 0.f;
        #pragma unroll
        for (int kk = 0; kk < 8; kk++)
            s += sm[lane + kk * 32] * conv_w[c * C_ + lane + kk * 32];
        #pragma unroll
        for (int o = 16; o > 0; o >>= 1) s += __shfl_xor_sync(0xffffffffu, s, o);
        float g = fmaxf(s + conv_b[c], 0.f);
        int idx = n * CM_ + c;
        if (lane < 25) g_wdyn[idx * 25 + lane] = fmaf(a1, fmaf(g, kw[lane],  kb[lane]),  b1);
        if (lane < 9)  g_watr[idx * 9  + lane] = fmaf(a2, fmaf(g, k2w[lane], k2b[lane]), b2);
    }
}

// ---------------- kernel 3: depthwise convs (R12 winner, unchanged) ----------------
__global__ __launch_bounds__(256) void dw_kernel(
    const float* __restrict__ adap_b, const float* __restrict__ atrous_b)
{
    __shared__ float sf[36][100];
    __shared__ float w5[25], w3[9];
    int t  = threadIdx.x;
    int rc = blockIdx.x;   // 0..2 (32-row chunks)
    int c  = blockIdx.y;
    int n  = blockIdx.z;
    int r0 = rc * 32;
    const __half* fp = g_fh + ((size_t)n * CM_ + c) * HW_;

    for (int idx = t; idx < 432; idx += 256) {
        int i = idx / 12, ck = idx - i * 12;
        int grow = r0 - 2 + i;
        float* dst = &sf[i][2 + ck * 8];
        if (grow >= 0 && grow < H_) {
            uint4 q = *(const uint4*)(fp + grow * W_ + ck * 8);
            const __half2* h = (const __half2*)&q;
            *(float2*)(dst + 0) = __half22float2(h[0]);
            *(float2*)(dst + 2) = __half22float2(h[1]);
            *(float2*)(dst + 4) = __half22float2(h[2]);
            *(float2*)(dst + 6) = __half22float2(h[3]);
        } else {
            *(float2*)(dst + 0) = make_float2(0.f, 0.f);
            *(float2*)(dst + 2) = make_float2(0.f, 0.f);
            *(float2*)(dst + 4) = make_float2(0.f, 0.f);
            *(float2*)(dst + 6) = make_float2(0.f, 0.f);
        }
    }
    if (t < 144) {
        int i = t / 4, b = t & 3;
        int j = (b < 2) ? b : 96 + b;   // 0,1,98,99
        sf[i][j] = 0.f;
    }
    if (t < 25) w5[t] = g_wdyn[((size_t)n * CM_ + c) * 25 + t];
    if (t < 9)  w3[t] = g_watr[((size_t)n * CM_ + c) * 9 + t];
    __syncthreads();

    float ab  = adap_b[c];
    float atb = atrous_b[c];
    __half* o0 = g_dwh0 + ((size_t)n * CM_ + c) * HW_;
    __half* o1 = g_dwh1 + ((size_t)n * CM_ + c) * HW_;

    for (int task = t; task < 384; task += 256) {
        int rg = task / 48;
        int c0 = (task - rg * 48) * 2;
        float s[8][6];
        #pragma unroll
        for (int i = 0; i < 8; ++i)
            #pragma unroll
            for (int j = 0; j < 6; ++j)
                s[i][j] = sf[rg * 4 + i][c0 + j];

        float a5[4][2], a3[4][2];
        #pragma unroll
        for (int rr = 0; rr < 4; ++rr) {
            a5[rr][0] = ab;  a5[rr][1] = ab;
            a3[rr][0] = atb; a3[rr][1] = atb;
        }
        #pragma unroll
        for (int i = 0; i < 5; ++i)
            #pragma unroll
            for (int j = 0; j < 5; ++j) {
                float w = w5[i * 5 + j];
                #pragma unroll
                for (int rr = 0; rr < 4; ++rr) {
                    a5[rr][0] = fmaf(w, s[rr + i][j],     a5[rr][0]);
                    a5[rr][1] = fmaf(w, s[rr + i][j + 1], a5[rr][1]);
                }
            }
        #pragma unroll
        for (int i = 0; i < 3; ++i)
            #pragma unroll
            for (int j = 0; j < 3; ++j) {
                float w = w3[i * 3 + j];
                #pragma unroll
                for (int rr = 0; rr < 4; ++rr) {
                    a3[rr][0] = fmaf(w, s[rr + 2 * i][2 * j],     a3[rr][0]);
                    a3[rr][1] = fmaf(w, s[rr + 2 * i][2 * j + 1], a3[rr][1]);
                }
            }

        int rbase = r0 + rg * 4;
        #pragma unroll
        for (int rr = 0; rr < 4; ++rr) {
            *(__half2*)&o0[(rbase + rr) * W_ + c0] =
                __floats2half2_rn(a5[rr][0], a5[rr][1]);
            *(__half2*)&o1[(rbase + rr) * W_ + c0] =
                __floats2half2_rn(a3[rr][0], a3[rr][1]);
        }
    }
}

// ---------------- kernel 4: fuse GEMM, both out-halves per block ----------------
// B-fragment prefetch + one-deep A-fragment pipeline; weight convert at fill.
__global__ __launch_bounds__(256) void fuse_mma(
    float* __restrict__ out,
    const float* __restrict__ fuse_w,
    const float* __restrict__ fuse_b)
{
    extern __shared__ __align__(16) char smraw[];
    __half* As  = (__half*)smraw;              // [64][128] halves, 16 KB
    __half* Bs0 = (__half*)(smraw + 16384);    // [64][64] halves, 8 KB
    __half* Bs1 = (__half*)(smraw + 24576);    // 8 KB
    float* stg  = (float*)(smraw + 32768);     // staging, 8*1152*4 = 36864 B

    int t = threadIdx.x, lane = t & 31, warp = t >> 5;
    int gq = lane >> 2, gr = lane & 3;
    int l8 = lane & 7, grp = lane >> 3;
    int n = blockIdx.y;
    int br = blockIdx.z;
    int base = blockIdx.x * 128;
    int wm = warp & 3, wn = warp >> 2;
    const __half* dwp = (br ? g_dwh1 : g_dwh0) + (size_t)n * CM_ * HW_ + base;

    // A tile via cp.async
    #pragma unroll
    for (int i = 0; i < 4; ++i) {
        int idx = t + i * 256;
        int c = idx >> 4, ch = idx & 15;
        cp16(smem_u32(As + c * 128 + ((ch ^ (c & 7)) << 3)),
             dwp + (size_t)c * HW_ + ch * 8);
    }
    CP_COMMIT();
    // B tiles: load fp32 fuse_w, convert, swizzled STS (overlaps A cp.async)
    #pragma unroll
    for (int i = 0; i < 4; ++i) {
        int idx = t + i * 256;
        int oh = idx >> 9;
        int rem = idx & 511;
        int o = rem >> 3, ch = rem & 7;
        __half* Bd = oh ? Bs1 : Bs0;
        const float* src = fuse_w + (size_t)(oh * 64 + o) * 64 + ch * 8;
        float4 f0 = *(const float4*)src;
        float4 f1 = *(const float4*)(src + 4);
        *(uint4*)(Bd + o * 64 + ((ch ^ (o & 7)) << 3)) = cvt8h(f0, f1);
    }
    CP_WAIT(0);
    __syncthreads();

    int c4 = lane & 7, orow = lane >> 3;

    #define LOADA(buf, kk) do {                                              \
        _Pragma("unroll")                                                    \
        for (int mt = 0; mt < 2; ++mt) {                                     \
            int k  = (kk) * 16 + ((grp >> 1) << 3) + l8;                     \
            int px = wm * 32 + mt * 16 + ((grp & 1) << 3);                   \
            uint32_t addr = smem_u32(As + k * 128 + (((px >> 3) ^ (k & 7)) << 3)); \
            asm volatile(                                                    \
                "ldmatrix.sync.aligned.m8n8.x4.trans.shared.b16 {%0,%1,%2,%3}, [%4];" \
                : "=r"((buf)[mt][0]), "=r"((buf)[mt][1]),                    \
                  "=r"((buf)[mt][2]), "=r"((buf)[mt][3])                     \
                : "r"(addr));                                                \
        }                                                                    \
    } while (0)

    #pragma unroll
    for (int oh = 0; oh < 2; ++oh) {
        __half* Bc = oh ? Bs1 : Bs0;
        float acc[2][4][4];
        #pragma unroll
        for (int a = 0; a < 2; a++)
            #pragma unroll
            for (int b = 0; b < 4; b++)
                #pragma unroll
                for (int c = 0; c < 4; c++) acc[a][b][c] = 0.f;

        uint32_t af[2][2][4];
        LOADA(af[0], 0);
        #pragma unroll
        for (int kk = 0; kk < 4; ++kk) {
            uint32_t (*a)[4] = af[kk & 1];
            // prefetch all B fragments for this k16 group
            uint32_t bf[4][2];
            #pragma unroll
            for (int nt = 0; nt < 4; ++nt) {
                int nrow = wn * 32 + nt * 8 + l8;
                int kc = kk * 2 + (grp & 1);
                uint32_t baddr = smem_u32(Bc + nrow * 64 + ((kc ^ (nrow & 7)) << 3));
                asm volatile(
                    "ldmatrix.sync.aligned.m8n8.x2.shared.b16 {%0,%1}, [%2];"
                    : "=r"(bf[nt][0]), "=r"(bf[nt][1]) : "r"(baddr));
            }
            // one-deep A pipeline: issue next k16's A loads before the mma chain
            if (kk < 3) LOADA(af[(kk + 1) & 1], kk + 1);
            #pragma unroll
            for (int nt = 0; nt < 4; ++nt) {
                mma16(acc[0][nt], a[0], bf[nt][0], bf[nt][1]);
                mma16(acc[1][nt], a[1], bf[nt][0], bf[nt][1]);
            }
        }

        // ---- epilogue: [oc][px] stride-36 staging, float4 loads + STG.128 ----
        float* st = stg + warp * 1152;
        __syncwarp();
        #pragma unroll
        for (int mt = 0; mt < 2; ++mt)
            #pragma unroll
            for (int nt = 0; nt < 4; ++nt) {
                int pr = mt * 16 + gq, oc = nt * 8 + 2 * gr;
                st[oc * 36 + pr]           = acc[mt][nt][0];
                st[(oc + 1) * 36 + pr]     = acc[mt][nt][1];
                st[oc * 36 + pr + 8]       = acc[mt][nt][2];
                st[(oc + 1) * 36 + pr + 8] = acc[mt][nt][3];
            }
        __syncwarp();
        float* yp = out + ((size_t)n * 256 + (size_t)br * 128 + (size_t)oh * 64 + (size_t)wn * 32) * HW_
                    + base + wm * 32;
        #pragma unroll
        for (int it = 0; it < 8; ++it) {
            int o = it * 4 + orow;
            float4 vv = *(const float4*)&st[o * 36 + c4 * 4];
            float bv = fuse_b[oh * 64 + wn * 32 + o];
            vv.x += bv; vv.y += bv; vv.z += bv; vv.w += bv;
            *(float4*)(yp + (size_t)o * HW_ + c4 * 4) = vv;
        }
    }
    #undef LOADA
}

// ---------------- launcher ----------------
#define CONV1_SMEM 49152             // Bs 32K + 2x A 8K; staging (36864) fits
#define FUSE_SMEM  (32768 + 36864)   // tiles 32K + staging 36864

extern "C" void kernel_launch(void* const* d_in, const int* in_sizes, int n_in,
                              void* d_out, int out_size) {
    const float* x        = (const float*)d_in[0];
    const float* conv_w   = (const float*)d_in[1];
    const float* conv_b   = (const float*)d_in[2];
    const float* ckw      = (const float*)d_in[3];
    const float* ckb      = (const float*)d_in[4];
    const float* ck2w     = (const float*)d_in[5];
    const float* ck2b     = (const float*)d_in[6];
    const float* kw       = (const float*)d_in[7];
    const float* kb       = (const float*)d_in[8];
    const float* k2w      = (const float*)d_in[9];
    const float* k2b      = (const float*)d_in[10];
    const float* fuse_w   = (const float*)d_in[11];
    const float* fuse_b   = (const float*)d_in[12];
    const float* adap_b   = (const float*)d_in[13];
    const float* atrous_b = (const float*)d_in[14];
    float* out = (float*)d_out;

    cudaFuncSetAttribute(conv1_mma, cudaFuncAttributeMaxDynamicSharedMemorySize, CONV1_SMEM);
    cudaFuncSetAttribute(fuse_mma,  cudaFuncAttributeMaxDynamicSharedMemorySize, FUSE_SMEM);

    conv1_mma<<<dim3(NBLK_, N_), 256, CONV1_SMEM>>>(x, conv_b, conv_w);
    weights_kernel<<<N_, 256>>>(conv_w, conv_b, ckw, ckb, ck2w, ck2b, kw, kb, k2w, k2b);
    dw_kernel<<<dim3(3, CM_, N_), 256>>>(adap_b, atrous_b);
    fuse_mma<<<dim3(HW_ / 128, N_, 2), 256, FUSE_SMEM>>>(out, fuse_w, fuse_b);
}

// round 17
// speedup vs baseline: 1.1431x; 1.0027x over previous
#include <cuda_runtime.h>
#include <cuda_fp16.h>
#include <cstdint>

#define N_   16
#define C_   256
#define CM_  64
#define H_   96
#define W_   96
#define HW_  9216   // 96*96
#define NBLK_ 72    // conv1 blocks per image (HW/128)

// ---------------- scratch (device globals; no allocations) ----------------
__device__ float g_psum[N_ * NBLK_ * C_];
__device__ float g_wdyn[N_ * CM_ * 25];
__device__ float g_watr[N_ * CM_ * 9];
__device__ __half g_fh [N_ * CM_ * HW_];    // f = relu(1x1 conv) in fp16
__device__ __half g_dwh0[N_ * CM_ * HW_];   // depthwise 5x5 out (fp16)
__device__ __half g_dwh1[N_ * CM_ * HW_];   // depthwise atrous out (fp16)

// ---------------- helpers ----------------
__device__ __forceinline__ void mma16(float* d, const uint32_t* a, uint32_t b0, uint32_t b1) {
    asm volatile(
        "mma.sync.aligned.m16n8k16.row.col.f32.f16.f16.f32 "
        "{%0,%1,%2,%3},{%4,%5,%6,%7},{%8,%9},{%0,%1,%2,%3};\n"
        : "+f"(d[0]), "+f"(d[1]), "+f"(d[2]), "+f"(d[3])
        : "r"(a[0]), "r"(a[1]), "r"(a[2]), "r"(a[3]), "r"(b0), "r"(b1));
}

__device__ __forceinline__ uint32_t smem_u32(const void* p) {
    return (uint32_t)__cvta_generic_to_shared(p);
}
__device__ __forceinline__ void cp16(uint32_t dst, const void* src) {
    asm volatile("cp.async.cg.shared.global [%0], [%1], 16;" :: "r"(dst), "l"(src));
}
#define CP_COMMIT() asm volatile("cp.async.commit_group;")
#define CP_WAIT(n)  asm volatile("cp.async.wait_group %0;" :: "n"(n))

// convert 8 consecutive fp32 -> 8 halves packed in uint4
__device__ __forceinline__ uint4 cvt8h(float4 f0, float4 f1) {
    __half2 h0 = __floats2half2_rn(f0.x, f0.y);
    __half2 h1 = __floats2half2_rn(f0.z, f0.w);
    __half2 h2 = __floats2half2_rn(f1.x, f1.y);
    __half2 h3 = __floats2half2_rn(f1.z, f1.w);
    uint4 q;
    q.x = *(uint32_t*)&h0; q.y = *(uint32_t*)&h1;
    q.z = *(uint32_t*)&h2; q.w = *(uint32_t*)&h3;
    return q;
}

// ---------------- kernel 1: 1x1 conv via fp16 mma + ldmatrix ----------------
// Block tile: 128 px (M) x 64 outs (N), K=256 in 8 slabs of 32.
// Weights converted fp32->fp16 during smem fill; min 3 blocks/SM.
__global__ __launch_bounds__(256, 3) void conv1_mma(
    const float* __restrict__ x,
    const float* __restrict__ conv_b,
    const float* __restrict__ conv_w)
{
    extern __shared__ __align__(16) char smraw[];
    __half* Bs  = (__half*)smraw;              // [64][256] halves, 32 KB
    __half* As0 = (__half*)(smraw + 32768);    // [32][128] halves, 8 KB
    __half* As1 = (__half*)(smraw + 40960);    // 8 KB
    float* smf  = (float*)smraw;               // staging overlay (after final sync)

    int t = threadIdx.x, lane = t & 31, warp = t >> 5;
    int gq = lane >> 2, gr = lane & 3;
    int l8 = lane & 7, grp = lane >> 3;
    int n = blockIdx.y, blk = blockIdx.x;
    int base = blk * 128;
    int wm = warp & 3, wn = warp >> 2;
    const float* xp = x + (size_t)n * C_ * HW_ + base;
    float* psp = g_psum + ((size_t)n * NBLK_ + blk) * C_;

    // ---- B fill: load fp32 conv_w, convert, swizzled STS (one-time) ----
    #pragma unroll
    for (int i = 0; i < 8; ++i) {
        int idx = t + i * 256;
        int o = idx >> 5, ch = idx & 31;
        const float* src = conv_w + o * 256 + ch * 8;
        float4 f0 = *(const float4*)src;
        float4 f1 = *(const float4*)(src + 4);
        *(uint4*)(Bs + o * 256 + ((ch ^ (o & 7)) << 3)) = cvt8h(f0, f1);
    }

    int krow = t >> 3;
    int px0  = (t & 7) * 16;
    int ch0  = (t & 7) * 2;

    float4 v[4];
    #define LOAD_SLAB(s) do {                                            \
        const float* p_ = xp + (size_t)((s) * 32 + krow) * HW_ + px0;    \
        v[0] = *(const float4*)(p_);                                     \
        v[1] = *(const float4*)(p_ + 4);                                 \
        v[2] = *(const float4*)(p_ + 8);                                 \
        v[3] = *(const float4*)(p_ + 12);                                \
    } while (0)
    #define PSUM_WRITE(s) do {                                           \
        float s_ = v[0].x + v[0].y + v[0].z + v[0].w                     \
                 + v[1].x + v[1].y + v[1].z + v[1].w                     \
                 + v[2].x + v[2].y + v[2].z + v[2].w                     \
                 + v[3].x + v[3].y + v[3].z + v[3].w;                    \
        s_ += __shfl_down_sync(0xffffffffu, s_, 4, 8);                   \
        s_ += __shfl_down_sync(0xffffffffu, s_, 2, 8);                   \
        s_ += __shfl_down_sync(0xffffffffu, s_, 1, 8);                   \
        if ((t & 7) == 0) psp[(s) * 32 + krow] = s_;                     \
    } while (0)
    #define STORE_A2(As) do {                                            \
        *(uint4*)((As) + krow * 128 + ((ch0 ^ (krow & 7)) << 3)) = cvt8h(v[0], v[1]); \
        *(uint4*)((As) + krow * 128 + (((ch0 + 1) ^ (krow & 7)) << 3)) = cvt8h(v[2], v[3]); \
    } while (0)

    float acc[2][4][4];
    #pragma unroll
    for (int a = 0; a < 2; a++)
        #pragma unroll
        for (int b = 0; b < 4; b++)
            #pragma unroll
            for (int c = 0; c < 4; c++) acc[a][b][c] = 0.f;

    LOAD_SLAB(0);
    PSUM_WRITE(0);
    STORE_A2(As0);
    LOAD_SLAB(1);
    __syncthreads();

    for (int slab = 0; slab < 8; ++slab) {
        __half* Ac = (slab & 1) ? As1 : As0;
        #pragma unroll
        for (int g = 0; g < 2; ++g) {
            uint32_t a[2][4];
            #pragma unroll
            for (int mt = 0; mt < 2; ++mt) {
                int k  = g * 16 + ((grp >> 1) << 3) + l8;
                int px = wm * 32 + mt * 16 + ((grp & 1) << 3);
                uint32_t addr = smem_u32(Ac + k * 128 + (((px >> 3) ^ (k & 7)) << 3));
                asm volatile(
                    "ldmatrix.sync.aligned.m8n8.x4.trans.shared.b16 {%0,%1,%2,%3}, [%4];"
                    : "=r"(a[mt][0]), "=r"(a[mt][1]), "=r"(a[mt][2]), "=r"(a[mt][3])
                    : "r"(addr));
            }
            uint32_t bf[4][2];
            #pragma unroll
            for (int nt = 0; nt < 4; ++nt) {
                int nrow = wn * 32 + nt * 8 + l8;
                int kc = slab * 4 + g * 2 + (grp & 1);
                uint32_t baddr = smem_u32(Bs + nrow * 256 + ((kc ^ (nrow & 7)) << 3));
                asm volatile(
                    "ldmatrix.sync.aligned.m8n8.x2.shared.b16 {%0,%1}, [%2];"
                    : "=r"(bf[nt][0]), "=r"(bf[nt][1]) : "r"(baddr));
            }
            #pragma unroll
            for (int nt = 0; nt < 4; ++nt) {
                mma16(acc[0][nt], a[0], bf[nt][0], bf[nt][1]);
                mma16(acc[1][nt], a[1], bf[nt][0], bf[nt][1]);
            }
        }
        if (slab < 7) {
            PSUM_WRITE(slab + 1);
            STORE_A2((slab & 1) ? As0 : As1);
            if (slab < 6) LOAD_SLAB(slab + 2);
            __syncthreads();
        }
    }
    __syncthreads();

    // ---- epilogue: per-warp [oc][px] stride-36 staging, 8B half4 stores ----
    float* st = smf + warp * 1152;   // 32*36
    #pragma unroll
    for (int mt = 0; mt < 2; ++mt)
        #pragma unroll
        for (int nt = 0; nt < 4; ++nt) {
            int pr = mt * 16 + gq, oc = nt * 8 + 2 * gr;
            st[oc * 36 + pr]           = acc[mt][nt][0];
            st[(oc + 1) * 36 + pr]     = acc[mt][nt][1];
            st[oc * 36 + pr + 8]       = acc[mt][nt][2];
            st[(oc + 1) * 36 + pr + 8] = acc[mt][nt][3];
        }
    __syncwarp();
    __half* fp = g_fh + (size_t)n * CM_ * HW_ + base + wm * 32;
    int c4 = lane & 7, orow = lane >> 3;
    #pragma unroll
    for (int it = 0; it < 8; ++it) {
        int o = it * 4 + orow;
        float4 vv = *(const float4*)&st[o * 36 + c4 * 4];
        float bv = conv_b[wn * 32 + o];
        __half2 h01 = __floats2half2_rn(fmaxf(vv.x + bv, 0.f), fmaxf(vv.y + bv, 0.f));
        __half2 h23 = __floats2half2_rn(fmaxf(vv.z + bv, 0.f), fmaxf(vv.w + bv, 0.f));
        uint2 q;
        q.x = *(uint32_t*)&h01; q.y = *(uint32_t*)&h23;
        *(uint2*)(fp + (size_t)(wn * 32 + o) * HW_ + c4 * 4) = q;
    }
    #undef LOAD_SLAB
    #undef PSUM_WRITE
    #undef STORE_A2
}

// ---------------- kernel 2: finish mean + g + dynamic depthwise weights ----------------
__global__ __launch_bounds__(256) void weights_kernel(
    const float* __restrict__ conv_w, const float* __restrict__ conv_b,
    const float* __restrict__ ckw,  const float* __restrict__ ckb,
    const float* __restrict__ ck2w, const float* __restrict__ ck2b,
    const float* __restrict__ kw,   const float* __restrict__ kb,
    const float* __restrict__ k2w,  const float* __restrict__ k2b)
{
    __shared__ float sm[C_];
    int n = blockIdx.x;
    int t = threadIdx.x;
    {
        const float* pp = g_psum + (size_t)n * NBLK_ * C_ + t;
        float s = 0.f;
        #pragma unroll 8
        for (int b = 0; b < NBLK_; ++b) s += pp[(size_t)b * C_];
        sm[t] = s * (1.0f / (float)HW_);
    }
    __syncthreads();
    int warp = t >> 5, lane = t & 31;
    float a1 = ckw[0],  b1 = ckb[0];
    float a2 = ck2w[0], b2 = ck2b[0];
    for (int c = warp; c < CM_; c += 8) {
        float s = 0.f;
        #pragma unroll
        for (int kk = 0; kk < 8; kk++)
            s += sm[lane + kk * 32] * conv_w[c * C_ + lane + kk * 32];
        #pragma unroll
        for (int o = 16; o > 0; o >>= 1) s += __shfl_xor_sync(0xffffffffu, s, o);
        float g = fmaxf(s + conv_b[c], 0.f);
        int idx = n * CM_ + c;
        if (lane < 25) g_wdyn[idx * 25 + lane] = fmaf(a1, fmaf(g, kw[lane],  kb[lane]),  b1);
        if (lane < 9)  g_watr[idx * 9  + lane] = fmaf(a2, fmaf(g, k2w[lane], k2b[lane]), b2);
    }
}

// ---------------- kernel 3: depthwise convs (R12 winner, unchanged) ----------------
__global__ __launch_bounds__(256) void dw_kernel(
    const float* __restrict__ adap_b, const float* __restrict__ atrous_b)
{
    __shared__ float sf[36][100];
    __shared__ float w5[25], w3[9];
    int t  = threadIdx.x;
    int rc = blockIdx.x;   // 0..2 (32-row chunks)
    int c  = blockIdx.y;
    int n  = blockIdx.z;
    int r0 = rc * 32;
    const __half* fp = g_fh + ((size_t)n * CM_ + c) * HW_;

    for (int idx = t; idx < 432; idx += 256) {
        int i = idx / 12, ck = idx - i * 12;
        int grow = r0 - 2 + i;
        float* dst = &sf[i][2 + ck * 8];
        if (grow >= 0 && grow < H_) {
            uint4 q = *(const uint4*)(fp + grow * W_ + ck * 8);
            const __half2* h = (const __half2*)&q;
            *(float2*)(dst + 0) = __half22float2(h[0]);
            *(float2*)(dst + 2) = __half22float2(h[1]);
            *(float2*)(dst + 4) = __half22float2(h[2]);
            *(float2*)(dst + 6) = __half22float2(h[3]);
        } else {
            *(float2*)(dst + 0) = make_float2(0.f, 0.f);
            *(float2*)(dst + 2) = make_float2(0.f, 0.f);
            *(float2*)(dst + 4) = make_float2(0.f, 0.f);
            *(float2*)(dst + 6) = make_float2(0.f, 0.f);
        }
    }
    if (t < 144) {
        int i = t / 4, b = t & 3;
        int j = (b < 2) ? b : 96 + b;   // 0,1,98,99
        sf[i][j] = 0.f;
    }
    if (t < 25) w5[t] = g_wdyn[((size_t)n * CM_ + c) * 25 + t];
    if (t < 9)  w3[t] = g_watr[((size_t)n * CM_ + c) * 9 + t];
    __syncthreads();

    float ab  = adap_b[c];
    float atb = atrous_b[c];
    __half* o0 = g_dwh0 + ((size_t)n * CM_ + c) * HW_;
    __half* o1 = g_dwh1 + ((size_t)n * CM_ + c) * HW_;

    for (int task = t; task < 384; task += 256) {
        int rg = task / 48;
        int c0 = (task - rg * 48) * 2;
        float s[8][6];
        #pragma unroll
        for (int i = 0; i < 8; ++i)
            #pragma unroll
            for (int j = 0; j < 6; ++j)
                s[i][j] = sf[rg * 4 + i][c0 + j];

        float a5[4][2], a3[4][2];
        #pragma unroll
        for (int rr = 0; rr < 4; ++rr) {
            a5[rr][0] = ab;  a5[rr][1] = ab;
            a3[rr][0] = atb; a3[rr][1] = atb;
        }
        #pragma unroll
        for (int i = 0; i < 5; ++i)
            #pragma unroll
            for (int j = 0; j < 5; ++j) {
                float w = w5[i * 5 + j];
                #pragma unroll
                for (int rr = 0; rr < 4; ++rr) {
                    a5[rr][0] = fmaf(w, s[rr + i][j],     a5[rr][0]);
                    a5[rr][1] = fmaf(w, s[rr + i][j + 1], a5[rr][1]);
                }
            }
        #pragma unroll
        for (int i = 0; i < 3; ++i)
            #pragma unroll
            for (int j = 0; j < 3; ++j) {
                float w = w3[i * 3 + j];
                #pragma unroll
                for (int rr = 0; rr < 4; ++rr) {
                    a3[rr][0] = fmaf(w, s[rr + 2 * i][2 * j],     a3[rr][0]);
                    a3[rr][1] = fmaf(w, s[rr + 2 * i][2 * j + 1], a3[rr][1]);
                }
            }

        int rbase = r0 + rg * 4;
        #pragma unroll
        for (int rr = 0; rr < 4; ++rr) {
            *(__half2*)&o0[(rbase + rr) * W_ + c0] =
                __floats2half2_rn(a5[rr][0], a5[rr][1]);
            *(__half2*)&o1[(rbase + rr) * W_ + c0] =
                __floats2half2_rn(a3[rr][0], a3[rr][1]);
        }
    }
}

// ---------------- kernel 4: fuse GEMM, both out-halves per block ----------------
// B-fragment prefetch + one-deep A-fragment pipeline; min 3 blocks/SM.
__global__ __launch_bounds__(256, 3) void fuse_mma(
    float* __restrict__ out,
    const float* __restrict__ fuse_w,
    const float* __restrict__ fuse_b)
{
    extern __shared__ __align__(16) char smraw[];
    __half* As  = (__half*)smraw;              // [64][128] halves, 16 KB
    __half* Bs0 = (__half*)(smraw + 16384);    // [64][64] halves, 8 KB
    __half* Bs1 = (__half*)(smraw + 24576);    // 8 KB
    float* stg  = (float*)(smraw + 32768);     // staging, 8*1152*4 = 36864 B

    int t = threadIdx.x, lane = t & 31, warp = t >> 5;
    int gq = lane >> 2, gr = lane & 3;
    int l8 = lane & 7, grp = lane >> 3;
    int n = blockIdx.y;
    int br = blockIdx.z;
    int base = blockIdx.x * 128;
    int wm = warp & 3, wn = warp >> 2;
    const __half* dwp = (br ? g_dwh1 : g_dwh0) + (size_t)n * CM_ * HW_ + base;

    // A tile via cp.async
    #pragma unroll
    for (int i = 0; i < 4; ++i) {
        int idx = t + i * 256;
        int c = idx >> 4, ch = idx & 15;
        cp16(smem_u32(As + c * 128 + ((ch ^ (c & 7)) << 3)),
             dwp + (size_t)c * HW_ + ch * 8);
    }
    CP_COMMIT();
    // B tiles: load fp32 fuse_w, convert, swizzled STS (overlaps A cp.async)
    #pragma unroll
    for (int i = 0; i < 4; ++i) {
        int idx = t + i * 256;
        int oh = idx >> 9;
        int rem = idx & 511;
        int o = rem >> 3, ch = rem & 7;
        __half* Bd = oh ? Bs1 : Bs0;
        const float* src = fuse_w + (size_t)(oh * 64 + o) * 64 + ch * 8;
        float4 f0 = *(const float4*)src;
        float4 f1 = *(const float4*)(src + 4);
        *(uint4*)(Bd + o * 64 + ((ch ^ (o & 7)) << 3)) = cvt8h(f0, f1);
    }
    CP_WAIT(0);
    __syncthreads();

    int c4 = lane & 7, orow = lane >> 3;

    #define LOADA(buf, kk) do {                                              \
        _Pragma("unroll")                                                    \
        for (int mt = 0; mt < 2; ++mt) {                                     \
            int k  = (kk) * 16 + ((grp >> 1) << 3) + l8;                     \
            int px = wm * 32 + mt * 16 + ((grp & 1) << 3);                   \
            uint32_t addr = smem_u32(As + k * 128 + (((px >> 3) ^ (k & 7)) << 3)); \
            asm volatile(                                                    \
                "ldmatrix.sync.aligned.m8n8.x4.trans.shared.b16 {%0,%1,%2,%3}, [%4];" \
                : "=r"((buf)[mt][0]), "=r"((buf)[mt][1]),                    \
                  "=r"((buf)[mt][2]), "=r"((buf)[mt][3])                     \
                : "r"(addr));                                                \
        }                                                                    \
    } while (0)

    #pragma unroll
    for (int oh = 0; oh < 2; ++oh) {
        __half* Bc = oh ? Bs1 : Bs0;
        float acc[2][4][4];
        #pragma unroll
        for (int a = 0; a < 2; a++)
            #pragma unroll
            for (int b = 0; b < 4; b++)
                #pragma unroll
                for (int c = 0; c < 4; c++) acc[a][b][c] = 0.f;

        uint32_t af[2][2][4];
        LOADA(af[0], 0);
        #pragma unroll
        for (int kk = 0; kk < 4; ++kk) {
            uint32_t (*a)[4] = af[kk & 1];
            // prefetch all B fragments for this k16 group
            uint32_t bf[4][2];
            #pragma unroll
            for (int nt = 0; nt < 4; ++nt) {
                int nrow = wn * 32 + nt * 8 + l8;
                int kc = kk * 2 + (grp & 1);
                uint32_t baddr = smem_u32(Bc + nrow * 64 + ((kc ^ (nrow & 7)) << 3));
                asm volatile(
                    "ldmatrix.sync.aligned.m8n8.x2.shared.b16 {%0,%1}, [%2];"
                    : "=r"(bf[nt][0]), "=r"(bf[nt][1]) : "r"(baddr));
            }
            // one-deep A pipeline: issue next k16's A loads before the mma chain
            if (kk < 3) LOADA(af[(kk + 1) & 1], kk + 1);
            #pragma unroll
            for (int nt = 0; nt < 4; ++nt) {
                mma16(acc[0][nt], a[0], bf[nt][0], bf[nt][1]);
                mma16(acc[1][nt], a[1], bf[nt][0], bf[nt][1]);
            }
        }

        // ---- epilogue: [oc][px] stride-36 staging, float4 loads + STG.128 ----
        float* st = stg + warp * 1152;
        __syncwarp();
        #pragma unroll
        for (int mt = 0; mt < 2; ++mt)
            #pragma unroll
            for (int nt = 0; nt < 4; ++nt) {
                int pr = mt * 16 + gq, oc = nt * 8 + 2 * gr;
                st[oc * 36 + pr]           = acc[mt][nt][0];
                st[(oc + 1) * 36 + pr]     = acc[mt][nt][1];
                st[oc * 36 + pr + 8]       = acc[mt][nt][2];
                st[(oc + 1) * 36 + pr + 8] = acc[mt][nt][3];
            }
        __syncwarp();
        float* yp = out + ((size_t)n * 256 + (size_t)br * 128 + (size_t)oh * 64 + (size_t)wn * 32) * HW_
                    + base + wm * 32;
        #pragma unroll
        for (int it = 0; it < 8; ++it) {
            int o = it * 4 + orow;
            float4 vv = *(const float4*)&st[o * 36 + c4 * 4];
            float bv = fuse_b[oh * 64 + wn * 32 + o];
            vv.x += bv; vv.y += bv; vv.z += bv; vv.w += bv;
            *(float4*)(yp + (size_t)o * HW_ + c4 * 4) = vv;
        }
    }
    #undef LOADA
}

// ---------------- launcher ----------------
#define CONV1_SMEM 49152             // Bs 32K + 2x A 8K; staging (36864) fits
#define FUSE_SMEM  (32768 + 36864)   // tiles 32K + staging 36864

extern "C" void kernel_launch(void* const* d_in, const int* in_sizes, int n_in,
                              void* d_out, int out_size) {
    const float* x        = (const float*)d_in[0];
    const float* conv_w   = (const float*)d_in[1];
    const float* conv_b   = (const float*)d_in[2];
    const float* ckw      = (const float*)d_in[3];
    const float* ckb      = (const float*)d_in[4];
    const float* ck2w     = (const float*)d_in[5];
    const float* ck2b     = (const float*)d_in[6];
    const float* kw       = (const float*)d_in[7];
    const float* kb       = (const float*)d_in[8];
    const float* k2w      = (const float*)d_in[9];
    const float* k2b      = (const float*)d_in[10];
    const float* fuse_w   = (const float*)d_in[11];
    const float* fuse_b   = (const float*)d_in[12];
    const float* adap_b   = (const float*)d_in[13];
    const float* atrous_b = (const float*)d_in[14];
    float* out = (float*)d_out;

    cudaFuncSetAttribute(conv1_mma, cudaFuncAttributeMaxDynamicSharedMemorySize, CONV1_SMEM);
    cudaFuncSetAttribute(fuse_mma,  cudaFuncAttributeMaxDynamicSharedMemorySize, FUSE_SMEM);

    conv1_mma<<<dim3(NBLK_, N_), 256, CONV1_SMEM>>>(x, conv_b, conv_w);
    weights_kernel<<<N_, 256>>>(conv_w, conv_b, ckw, ckb, ck2w, ck2b, kw, kb, k2w, k2b);
    dw_kernel<<<dim3(3, CM_, N_), 256>>>(adap_b, atrous_b);
    fuse_mma<<<dim3(HW_ / 128, N_, 2), 256, FUSE_SMEM>>>(out, fuse_w, fuse_b);
}